// round 11
// baseline (speedup 1.0000x reference)
#include <cuda_runtime.h>
#include <cuda_fp16.h>
#include <math.h>
#include <stdint.h>

#define BB 32
#define CC 512
#define HW 1024
#define DD 64
#define OO 640

// ---------------- scratch (device globals) ----------------
__device__ __half g_ht[(size_t)BB * HW * CC];    // h1^T [b][hw][c]
__device__ __half g_qkt[(size_t)BB * HW * 128];  // [b][hw][0:64=q,64:128=k]
__device__ __half g_v[(size_t)BB * CC * HW];     // V [b][c][hw]
__device__ __half g_st[(size_t)BB * HW * HW];    // S^T then P^T [b][k'][q]
__device__ __half g_xr[(size_t)BB * CC * HW];    // xr HALF [b][c][hw]
__device__ __half g_xrt[(size_t)BB * HW * CC];   // xr^T half [b][hw][c]
__device__ __half g_zt[(size_t)BB * HW * CC];    // z^T [b][hw][o]
__device__ __half g_wqh[OO * CC];                // W_qkv half [o][c]
__device__ __half g_w1f[CC * CC];                // (W1*bn2sc) half [o][c]
__device__ __half g_w2h[CC * CC];                // W2 half [c][o]
__device__ float  g_b1f[CC];
__device__ float  g_s1[CC], g_h1[CC], g_s2[CC], g_h2[CC];
__device__ float  g_psum[256 * CC];              // bn2 partials [slot][c]
__device__ float  g_psum2[256 * CC];

// ---------------- helpers ----------------
__device__ __forceinline__ float fexp(float x) {
    x = fmaxf(x, -87.0f);
    float t  = x * 1.4426950408889634f;
    float fi = floorf(t);
    float f  = t - fi;
    float r = 1.5403530e-4f;
    r = fmaf(r, f, 1.3333558e-3f);
    r = fmaf(r, f, 9.6181291e-3f);
    r = fmaf(r, f, 5.5504109e-2f);
    r = fmaf(r, f, 2.4022651e-1f);
    r = fmaf(r, f, 6.9314718e-1f);
    r = fmaf(r, f, 1.0f);
    return r * __int_as_float(((int)fi + 127) << 23);
}
__device__ __forceinline__ void cpa16(void* s, const void* g) {
    unsigned ss = (unsigned)__cvta_generic_to_shared(s);
    asm volatile("cp.async.cg.shared.global [%0], [%1], 16;\n" :: "r"(ss), "l"(g));
}
__device__ __forceinline__ void mma16(float* c, const uint32_t* a, const uint32_t* b) {
    asm volatile(
        "mma.sync.aligned.m16n8k16.row.col.f32.f16.f16.f32 "
        "{%0,%1,%2,%3}, {%4,%5,%6,%7}, {%8,%9}, {%0,%1,%2,%3};\n"
        : "+f"(c[0]), "+f"(c[1]), "+f"(c[2]), "+f"(c[3])
        : "r"(a[0]), "r"(a[1]), "r"(a[2]), "r"(a[3]), "r"(b[0]), "r"(b[1]));
}
__device__ __forceinline__ void ldsm4(uint32_t* r, uint32_t addr) {
    asm volatile("ldmatrix.sync.aligned.m8n8.x4.shared.b16 {%0,%1,%2,%3}, [%4];"
        : "=r"(r[0]), "=r"(r[1]), "=r"(r[2]), "=r"(r[3]) : "r"(addr));
}

// ---------------- fp16 tensor GEMM ----------------
// C[m,n] = alpha * sum_k A[m][k] * B[n][k]; CTA 128x128, 8 warps (2m x 4n),
// k-stage 32, 3-stage cp.async ring, occupancy 2.
// EPI: 0 = half store + bias[n]
//      1 = half store * alpha
//      3 = half store + bias[n] + relu
//      5 = half store + bias[m]
//      6 = half store + fp32 res, plus: xrt (half, transposed) + bn2 partials
//      7 = fp32 store + bias[m] + half res
#define RSTR 40                    // 32 + 8 halves pad
#define ASTG (128 * RSTR)
#define SMB  (3 * 2 * ASTG * 2)    // 61440 bytes

template <int EPI>
__global__ void __launch_bounds__(256, 2) hgemm(
    const __half* __restrict__ A, const __half* __restrict__ B, void* __restrict__ Cv,
    int K, int lda, int ldb, int ldc,
    long sA, long sB, long sC,
    const float* __restrict__ bias,
    const void* __restrict__ resv, long sRes,
    __half* __restrict__ aux, long sAux,
    float* __restrict__ ps, float* __restrict__ ps2,
    float alpha)
{
    extern __shared__ __align__(16) __half smh[];
    __half* As = smh;                  // 3 stages A
    __half* Bs = smh + 3 * ASTG;       // 3 stages B

    const int bz = blockIdx.z;
    const int n0 = blockIdx.x * 128;
    const int m0 = blockIdx.y * 128;
    const int tid = threadIdx.x;
    const int warp = tid >> 5;
    const int lane = tid & 31;
    const int wm = warp & 1;
    const int wn = warp >> 1;
    const int g = lane >> 2;
    const int tg = lane & 3;

    const uint32_t smb = (uint32_t)__cvta_generic_to_shared(smh);

    const int a_row = lane & 15;
    const int a_kb  = (lane >> 4) << 3;

    const __half* Ab = A + (size_t)bz * sA;
    const __half* Bb = B + (size_t)bz * sB;

    float acc[4][4][4];
    #pragma unroll
    for (int i = 0; i < 4; i++)
        #pragma unroll
        for (int j = 0; j < 4; j++)
            #pragma unroll
            for (int r = 0; r < 4; r++) acc[i][j][r] = 0.f;

    auto loadStage = [&](int st, int k0) {
        __half* Ad = As + st * ASTG;
        __half* Bd = Bs + st * ASTG;
        #pragma unroll
        for (int j = 0; j < 2; j++) {
            int id = tid + j * 256;
            int row = id >> 2, part = id & 3;
            cpa16(Ad + row * RSTR + part * 8,
                  Ab + (size_t)(m0 + row) * lda + k0 + part * 8);
            cpa16(Bd + row * RSTR + part * 8,
                  Bb + (size_t)(n0 + row) * ldb + k0 + part * 8);
        }
        asm volatile("cp.async.commit_group;\n");
    };

    const int T = K >> 5;
    loadStage(0, 0);
    if (T > 1) loadStage(1, 32);

    for (int t = 0; t < T; t++) {
        if (t + 1 < T) asm volatile("cp.async.wait_group 1;\n");
        else           asm volatile("cp.async.wait_group 0;\n");
        __syncthreads();
        if (t + 2 < T) loadStage((t + 2) % 3, (t + 2) << 5);

        const int st = t % 3;
        const uint32_t Aoff = smb + (uint32_t)(st * ASTG) * 2u;
        const uint32_t Boff = smb + (uint32_t)((3 + st) * ASTG) * 2u;
        #pragma unroll
        for (int kk = 0; kk < 32; kk += 16) {
            uint32_t a[4][4], bfr[4][2];
            #pragma unroll
            for (int mi = 0; mi < 4; mi++)
                ldsm4(a[mi], Aoff + (uint32_t)(((wm * 64 + mi * 16 + a_row) * RSTR) + kk + a_kb) * 2u);
            #pragma unroll
            for (int np = 0; np < 2; np++) {
                uint32_t r[4];
                ldsm4(r, Boff + (uint32_t)(((wn * 32 + np * 16 + a_row) * RSTR) + kk + a_kb) * 2u);
                bfr[np * 2][0]     = r[0];
                bfr[np * 2 + 1][0] = r[1];
                bfr[np * 2][1]     = r[2];
                bfr[np * 2 + 1][1] = r[3];
            }
            #pragma unroll
            for (int mi = 0; mi < 4; mi++)
                #pragma unroll
                for (int ni = 0; ni < 4; ni++)
                    mma16(acc[mi][ni], a[mi], bfr[ni]);
        }
    }

    // ---------------- epilogue ----------------
    __half* Ch = (__half*)Cv + (size_t)bz * sC;
    float*  Cf = (float*)Cv + (size_t)bz * sC;
    const float*  Rf = (EPI == 6) ? ((const float*)resv + (size_t)bz * sRes) : nullptr;
    const __half* Rh = (EPI == 7) ? ((const __half*)resv + (size_t)bz * sRes) : nullptr;

    if (EPI == 6) __syncthreads();   // stage smem reused below
    __half* smT = smh;               // [128][136] half (EPI 6)
    float*  pS  = (float*)(smh + 128 * 136);
    float*  pS2 = pS + 512;

    #pragma unroll
    for (int mi = 0; mi < 4; mi++) {
        int mr = m0 + wm * 64 + mi * 16 + g;
        float bm0 = 0.f, bm8 = 0.f;
        if (EPI == 5 || EPI == 7) { bm0 = bias[mr]; bm8 = bias[mr + 8]; }
        float rs0 = 0.f, rq0 = 0.f, rs8 = 0.f, rq8 = 0.f;
        #pragma unroll
        for (int ni = 0; ni < 4; ni++) {
            int nc = n0 + wn * 32 + ni * 8 + tg * 2;
            float v0 = acc[mi][ni][0], v1 = acc[mi][ni][1];
            float v2 = acc[mi][ni][2], v3 = acc[mi][ni][3];
            if (EPI == 1) { v0 *= alpha; v1 *= alpha; v2 *= alpha; v3 *= alpha; }
            if (EPI == 0 || EPI == 3) {
                float b0 = bias[nc], b1 = bias[nc + 1];
                v0 += b0; v1 += b1; v2 += b0; v3 += b1;
            }
            if (EPI == 3) {
                v0 = fmaxf(v0, 0.f); v1 = fmaxf(v1, 0.f);
                v2 = fmaxf(v2, 0.f); v3 = fmaxf(v3, 0.f);
            }
            if (EPI == 5 || EPI == 7) { v0 += bm0; v1 += bm0; v2 += bm8; v3 += bm8; }
            if (EPI == 7) {
                float2 r0 = __half22float2(*(const __half2*)(Rh + (size_t)mr * ldc + nc));
                float2 r8 = __half22float2(*(const __half2*)(Rh + (size_t)(mr + 8) * ldc + nc));
                v0 += r0.x; v1 += r0.y; v2 += r8.x; v3 += r8.y;
                *(float2*)(Cf + (size_t)mr * ldc + nc) = make_float2(v0, v1);
                *(float2*)(Cf + (size_t)(mr + 8) * ldc + nc) = make_float2(v2, v3);
            } else if (EPI == 6) {
                float2 r0 = *(const float2*)(Rf + (size_t)mr * ldc + nc);
                float2 r8 = *(const float2*)(Rf + (size_t)(mr + 8) * ldc + nc);
                v0 += r0.x; v1 += r0.y; v2 += r8.x; v3 += r8.y;
                *(__half2*)(Ch + (size_t)mr * ldc + nc) = __floats2half2_rn(v0, v1);
                *(__half2*)(Ch + (size_t)(mr + 8) * ldc + nc) = __floats2half2_rn(v2, v3);
                int ml = wm * 64 + mi * 16 + g;
                int nl = wn * 32 + ni * 8 + tg * 2;
                smT[(nl + 0) * 136 + ml]     = __float2half(v0);
                smT[(nl + 1) * 136 + ml]     = __float2half(v1);
                smT[(nl + 0) * 136 + ml + 8] = __float2half(v2);
                smT[(nl + 1) * 136 + ml + 8] = __float2half(v3);
                rs0 += v0 + v1; rq0 += v0 * v0 + v1 * v1;
                rs8 += v2 + v3; rq8 += v2 * v2 + v3 * v3;
            } else {
                *(__half2*)(Ch + (size_t)mr * ldc + nc) = __floats2half2_rn(v0, v1);
                *(__half2*)(Ch + (size_t)(mr + 8) * ldc + nc) = __floats2half2_rn(v2, v3);
            }
        }
        if (EPI == 6) {
            rs0 += __shfl_xor_sync(0xffffffffu, rs0, 1);
            rs0 += __shfl_xor_sync(0xffffffffu, rs0, 2);
            rq0 += __shfl_xor_sync(0xffffffffu, rq0, 1);
            rq0 += __shfl_xor_sync(0xffffffffu, rq0, 2);
            rs8 += __shfl_xor_sync(0xffffffffu, rs8, 1);
            rs8 += __shfl_xor_sync(0xffffffffu, rs8, 2);
            rq8 += __shfl_xor_sync(0xffffffffu, rq8, 1);
            rq8 += __shfl_xor_sync(0xffffffffu, rq8, 2);
            if (tg == 0) {
                int rl = wm * 64 + mi * 16 + g;
                pS [wn * 128 + rl]     = rs0;
                pS2[wn * 128 + rl]     = rq0;
                pS [wn * 128 + rl + 8] = rs8;
                pS2[wn * 128 + rl + 8] = rq8;
            }
        }
    }

    if (EPI == 6) {
        __syncthreads();
        if (tid < 128) {
            float s = pS[tid] + pS[128 + tid] + pS[256 + tid] + pS[384 + tid];
            float q = pS2[tid] + pS2[128 + tid] + pS2[256 + tid] + pS2[384 + tid];
            int slot = bz * 8 + blockIdx.x;
            ps [slot * CC + m0 + tid] = s;
            ps2[slot * CC + m0 + tid] = q;
        }
        __half* Xt = aux + (size_t)bz * sAux;
        #pragma unroll 8
        for (int it = 0; it < 32; it++) {
            int idx = it * 256 + tid;
            int row = idx >> 6, col = idx & 63;
            __half2 h = *(__half2*)(smT + row * 136 + col * 2);
            *(__half2*)(Xt + (size_t)(n0 + row) * CC + m0 + col * 2) = h;
        }
    }
}

// ---------------- elementwise / prep kernels ----------------
__global__ void bn_stats_kernel(const float* __restrict__ x,
                                const float* __restrict__ gamma,
                                const float* __restrict__ beta,
                                float* __restrict__ scale,
                                float* __restrict__ shift) {
    int c = blockIdx.x;
    int tid = threadIdx.x;
    float s = 0.f, s2 = 0.f;
    const float* xc = x + (size_t)c * HW;
    for (int b = 0; b < BB; b++) {
        const float* p = xc + (size_t)b * CC * HW;
        #pragma unroll 4
        for (int i = tid; i < HW; i += 256) {
            float v = p[i];
            s += v; s2 = fmaf(v, v, s2);
        }
    }
    __shared__ float ss[256], ss2[256];
    ss[tid] = s; ss2[tid] = s2;
    __syncthreads();
    for (int o = 128; o > 0; o >>= 1) {
        if (tid < o) { ss[tid] += ss[tid + o]; ss2[tid] += ss2[tid + o]; }
        __syncthreads();
    }
    if (tid == 0) {
        const float invN = 1.0f / (BB * HW);
        float mean = ss[0] * invN;
        float var  = ss2[0] * invN - mean * mean;
        float sc = gamma[c] * rsqrtf(var + 1e-5f);
        scale[c] = sc;
        shift[c] = beta[c] - mean * sc;
    }
}

// combine bn2 partials (256 slots) -> scale/shift
__global__ void bn2_combine(const float* __restrict__ ps, const float* __restrict__ ps2,
                            const float* __restrict__ gamma, const float* __restrict__ beta,
                            float* __restrict__ scale, float* __restrict__ shift) {
    int c = blockIdx.x * 256 + threadIdx.x;
    float s = 0.f, q = 0.f;
    for (int sl = 0; sl < 256; sl++) {
        s += ps[sl * CC + c];
        q += ps2[sl * CC + c];
    }
    const float invN = 1.0f / (BB * HW);
    float mean = s * invN;
    float var  = q * invN - mean * mean;
    float sc = gamma[c] * rsqrtf(var + 1e-5f);
    scale[c] = sc;
    shift[c] = beta[c] - mean * sc;
}

// x [c][hw] fp32 -> h^T [hw][c] half with bn1+relu
__global__ void bnT_kernel(const float* __restrict__ x, const float* __restrict__ sc,
                           const float* __restrict__ sh, __half* __restrict__ o) {
    __shared__ float t[32][33];
    int b = blockIdx.z;
    int hw0 = blockIdx.x * 32, c0 = blockIdx.y * 32;
    int tx = threadIdx.x, ty = threadIdx.y;
    const float* I = x + (size_t)b * CC * HW;
    __half* O = o + (size_t)b * HW * CC;
    #pragma unroll
    for (int j = 0; j < 32; j += 8) {
        int c = c0 + ty + j;
        float v = I[(size_t)c * HW + hw0 + tx];
        t[ty + j][tx] = fmaxf(fmaf(v, sc[c], sh[c]), 0.f);
    }
    __syncthreads();
    #pragma unroll
    for (int j = 0; j < 32; j += 8)
        O[(size_t)(hw0 + ty + j) * CC + c0 + tx] = __float2half(t[tx][ty + j]);
}

__global__ void round_half(const float* __restrict__ in, __half* __restrict__ out) {
    int i = blockIdx.x * 256 + threadIdx.x;
    float4 v = ((const float4*)in)[i];
    ((__half2*)out)[i * 2]     = __floats2half2_rn(v.x, v.y);
    ((__half2*)out)[i * 2 + 1] = __floats2half2_rn(v.z, v.w);
}

__global__ void w1_fold(const float* __restrict__ W1, const float* __restrict__ b1,
                        const float* __restrict__ sc, const float* __restrict__ sh,
                        __half* __restrict__ w1f, float* __restrict__ b1f) {
    int o = blockIdx.x;
    int tid = threadIdx.x;
    float acc = 0.f;
    for (int k = tid; k < CC; k += 256) {
        float w = W1[o * CC + k];
        acc = fmaf(w, sh[k], acc);
        w1f[o * CC + k] = __float2half(w * sc[k]);
    }
    __shared__ float r[256];
    r[tid] = acc; __syncthreads();
    for (int ofs = 128; ofs > 0; ofs >>= 1) {
        if (tid < ofs) r[tid] += r[tid + ofs];
        __syncthreads();
    }
    if (tid == 0) b1f[o] = b1[o] + r[0];
}

// row softmax over contiguous 1024-half rows of S^T, in place (axis = q)
__global__ void softmax_row(__half* __restrict__ S) {
    int row = blockIdx.x * 8 + (threadIdx.x >> 5);
    int lane = threadIdx.x & 31;
    __half2* p = (__half2*)(S + (size_t)row * HW);
    float f[32];
    #pragma unroll
    for (int i = 0; i < 16; i++) {
        float2 v = __half22float2(p[i * 32 + lane]);
        f[i * 2] = v.x; f[i * 2 + 1] = v.y;
    }
    float m = -3.0e38f;
    #pragma unroll
    for (int i = 0; i < 32; i++) m = fmaxf(m, f[i]);
    #pragma unroll
    for (int o = 16; o > 0; o >>= 1) m = fmaxf(m, __shfl_xor_sync(0xffffffffu, m, o));
    float s = 0.f;
    #pragma unroll
    for (int i = 0; i < 32; i++) { f[i] = fexp(f[i] - m); s += f[i]; }
    #pragma unroll
    for (int o = 16; o > 0; o >>= 1) s += __shfl_xor_sync(0xffffffffu, s, o);
    float inv = 1.0f / s;
    #pragma unroll
    for (int i = 0; i < 16; i++)
        p[i * 32 + lane] = __floats2half2_rn(f[i * 2] * inv, f[i * 2 + 1] * inv);
}

// ---------------- launcher ----------------
extern "C" void kernel_launch(void* const* d_in, const int* in_sizes, int n_in,
                              void* d_out, int out_size) {
    const float* x     = (const float*)d_in[0];
    const float* bn1_g = (const float*)d_in[1];
    const float* bn1_b = (const float*)d_in[2];
    const float* W_qkv = (const float*)d_in[3];
    const float* b_qkv = (const float*)d_in[4];
    const float* bn2_g = (const float*)d_in[5];
    const float* bn2_b = (const float*)d_in[6];
    const float* W1    = (const float*)d_in[7];
    const float* b1    = (const float*)d_in[8];
    const float* W2    = (const float*)d_in[9];
    const float* b2    = (const float*)d_in[10];
    float* out = (float*)d_out;

    __half *p_ht, *p_qkt, *p_v, *p_st, *p_xr, *p_xrt, *p_zt, *p_wqh, *p_w1f, *p_w2h;
    float *p_b1f, *p_s1, *p_h1, *p_s2, *p_h2, *p_ps, *p_ps2;
    cudaGetSymbolAddress((void**)&p_ht,  g_ht);
    cudaGetSymbolAddress((void**)&p_qkt, g_qkt);
    cudaGetSymbolAddress((void**)&p_v,   g_v);
    cudaGetSymbolAddress((void**)&p_st,  g_st);
    cudaGetSymbolAddress((void**)&p_xr,  g_xr);
    cudaGetSymbolAddress((void**)&p_xrt, g_xrt);
    cudaGetSymbolAddress((void**)&p_zt,  g_zt);
    cudaGetSymbolAddress((void**)&p_wqh, g_wqh);
    cudaGetSymbolAddress((void**)&p_w1f, g_w1f);
    cudaGetSymbolAddress((void**)&p_w2h, g_w2h);
    cudaGetSymbolAddress((void**)&p_b1f, g_b1f);
    cudaGetSymbolAddress((void**)&p_s1,  g_s1);
    cudaGetSymbolAddress((void**)&p_h1,  g_h1);
    cudaGetSymbolAddress((void**)&p_s2,  g_s2);
    cudaGetSymbolAddress((void**)&p_h2,  g_h2);
    cudaGetSymbolAddress((void**)&p_ps,  g_psum);
    cudaGetSymbolAddress((void**)&p_ps2, g_psum2);

    cudaFuncSetAttribute(hgemm<0>, cudaFuncAttributeMaxDynamicSharedMemorySize, SMB);
    cudaFuncSetAttribute(hgemm<1>, cudaFuncAttributeMaxDynamicSharedMemorySize, SMB);
    cudaFuncSetAttribute(hgemm<3>, cudaFuncAttributeMaxDynamicSharedMemorySize, SMB);
    cudaFuncSetAttribute(hgemm<5>, cudaFuncAttributeMaxDynamicSharedMemorySize, SMB);
    cudaFuncSetAttribute(hgemm<6>, cudaFuncAttributeMaxDynamicSharedMemorySize, SMB);
    cudaFuncSetAttribute(hgemm<7>, cudaFuncAttributeMaxDynamicSharedMemorySize, SMB);

    const long sX  = (long)CC * HW;
    const long sHT = (long)HW * CC;
    const long sQK = (long)HW * 128;
    const long sS  = (long)HW * HW;

    // prep: weights to half, bn1 stats, h^T
    round_half<<<OO * CC / 1024, 256>>>(W_qkv, p_wqh);
    round_half<<<CC * CC / 1024, 256>>>(W2, p_w2h);
    bn_stats_kernel<<<CC, 256>>>(x, bn1_g, bn1_b, p_s1, p_h1);
    bnT_kernel<<<dim3(HW / 32, CC / 32, BB), dim3(32, 8)>>>(x, p_s1, p_h1, p_ht);

    // qk[hw][128] = h^T . Wqk^T + b_qkv[0:128]
    hgemm<0><<<dim3(1, 8, BB), 256, SMB>>>(
        p_ht, p_wqh, p_qkt, CC, CC, CC, 128,
        sHT, 0L, sQK, b_qkv, nullptr, 0L, nullptr, 0L, nullptr, nullptr, 1.0f);

    // V[c][hw] = Wv . h + b_qkv[128+c]
    hgemm<5><<<dim3(8, 4, BB), 256, SMB>>>(
        p_wqh + 128 * CC, p_ht, p_v, CC, CC, CC, HW,
        0L, sHT, sX, b_qkv + 128, nullptr, 0L, nullptr, 0L, nullptr, nullptr, 1.0f);

    // S^T[k'][q] = (K . Q^T)/8
    hgemm<1><<<dim3(8, 8, BB), 256, SMB>>>(
        p_qkt + 64, p_qkt, p_st, DD, 128, 128, HW,
        sQK, sQK, sS, nullptr, nullptr, 0L, nullptr, 0L, nullptr, nullptr, 0.125f);

    // P^T row softmax in place
    softmax_row<<<BB * HW / 8, 256>>>(p_st);

    // xr(half) = x + V . P ; fused: xrt (transposed half) + bn2 partial sums
    hgemm<6><<<dim3(8, 4, BB), 256, SMB>>>(
        p_v, p_st, p_xr, HW, HW, HW, HW,
        sX, sS, sX, nullptr, x, sX, p_xrt, sHT, p_ps, p_ps2, 1.0f);

    // bn2 combine + fold into W1
    bn2_combine<<<2, 256>>>(p_ps, p_ps2, bn2_g, bn2_b, p_s2, p_h2);
    w1_fold<<<CC, 256>>>(W1, b1, p_s2, p_h2, p_w1f, p_b1f);

    // z^T[hw][o] = relu(xr^T . W1'^T + b1')
    hgemm<3><<<dim3(4, 8, BB), 256, SMB>>>(
        p_xrt, p_w1f, p_zt, CC, CC, CC, CC,
        sHT, 0L, sHT, p_b1f, nullptr, 0L, nullptr, 0L, nullptr, nullptr, 1.0f);

    // out[c][hw] = xr(half) + W2 . z + b2
    hgemm<7><<<dim3(8, 4, BB), 256, SMB>>>(
        p_w2h, p_zt, out, CC, CC, CC, HW,
        0L, sHT, sX, b2, p_xr, sX, nullptr, 0L, nullptr, nullptr, 1.0f);
}

// round 14
// speedup vs baseline: 1.0794x; 1.0794x over previous
#include <cuda_runtime.h>
#include <cuda_fp16.h>
#include <math.h>
#include <stdint.h>

#define BB 32
#define CC 512
#define HW 1024
#define DD 64
#define OO 640

// ---------------- scratch (device globals) ----------------
__device__ __half g_ht[(size_t)BB * HW * CC];    // h1^T [b][hw][c]
__device__ __half g_qkt[(size_t)BB * HW * 128];  // [b][hw][0:64=q,64:128=k]
__device__ __half g_v[(size_t)BB * CC * HW];     // V [b][c][hw]
__device__ __half g_st[(size_t)BB * HW * HW];    // S^T then P^T [b][k'][q]
__device__ __half g_xr[(size_t)BB * CC * HW];    // xr HALF [b][c][hw]
__device__ __half g_xrt[(size_t)BB * HW * CC];   // xr^T half [b][hw][c]
__device__ __half g_zt[(size_t)BB * HW * CC];    // z^T [b][hw][o]
__device__ __half g_wqh[OO * CC];                // W_qkv half [o][c]
__device__ __half g_w1f[CC * CC];                // (W1*bn2sc) half [o][c]
__device__ __half g_w2h[CC * CC];                // W2 half [c][o]
__device__ float  g_b1f[CC];
__device__ float  g_s1[CC], g_h1[CC], g_s2[CC], g_h2[CC];
__device__ float  g_psum[256 * CC];              // bn2 partials [slot][c]
__device__ float  g_psum2[256 * CC];

// ---------------- helpers ----------------
__device__ __forceinline__ float fexp(float x) {
    x = fmaxf(x, -87.0f);
    float t  = x * 1.4426950408889634f;
    float fi = floorf(t);
    float f  = t - fi;
    float r = 1.5403530e-4f;
    r = fmaf(r, f, 1.3333558e-3f);
    r = fmaf(r, f, 9.6181291e-3f);
    r = fmaf(r, f, 5.5504109e-2f);
    r = fmaf(r, f, 2.4022651e-1f);
    r = fmaf(r, f, 6.9314718e-1f);
    r = fmaf(r, f, 1.0f);
    return r * __int_as_float(((int)fi + 127) << 23);
}
__device__ __forceinline__ void cpa16(void* s, const void* g) {
    unsigned ss = (unsigned)__cvta_generic_to_shared(s);
    asm volatile("cp.async.cg.shared.global [%0], [%1], 16;\n" :: "r"(ss), "l"(g));
}
__device__ __forceinline__ void mma16(float* c, const uint32_t* a, const uint32_t* b) {
    asm volatile(
        "mma.sync.aligned.m16n8k16.row.col.f32.f16.f16.f32 "
        "{%0,%1,%2,%3}, {%4,%5,%6,%7}, {%8,%9}, {%0,%1,%2,%3};\n"
        : "+f"(c[0]), "+f"(c[1]), "+f"(c[2]), "+f"(c[3])
        : "r"(a[0]), "r"(a[1]), "r"(a[2]), "r"(a[3]), "r"(b[0]), "r"(b[1]));
}
__device__ __forceinline__ void ldsm4(uint32_t* r, uint32_t addr) {
    asm volatile("ldmatrix.sync.aligned.m8n8.x4.shared.b16 {%0,%1,%2,%3}, [%4];"
        : "=r"(r[0]), "=r"(r[1]), "=r"(r[2]), "=r"(r[3]) : "r"(addr));
}
__device__ __forceinline__ void ldsm2(uint32_t* r, uint32_t addr) {
    asm volatile("ldmatrix.sync.aligned.m8n8.x2.shared.b16 {%0,%1}, [%2];"
        : "=r"(r[0]), "=r"(r[1]) : "r"(addr));
}

// ---------------- fp16 tensor GEMM ----------------
// C[m,n] = alpha * sum_k A[m][k] * B[n][k]; CTA 128x128, 8 warps (2m x 4n),
// k-stage 32, 3-stage cp.async ring, occupancy 2.  (R10 mainloop, unchanged)
// EPI: 0 = half store + bias[n]
//      1 = half store * alpha
//      3 = half store + bias[n] + relu
//      5 = half store + bias[m]
//      6 = half store + fp32 res, plus: xrt (half, transposed) + bn2 partials
//      7 = fp32 store + bias[m] + half res
#define RSTR 40                    // 32 + 8 halves pad
#define ASTG (128 * RSTR)
#define SMB  (3 * 2 * ASTG * 2)    // 61440 bytes

template <int EPI>
__global__ void __launch_bounds__(256, 2) hgemm(
    const __half* __restrict__ A, const __half* __restrict__ B, void* __restrict__ Cv,
    int K, int lda, int ldb, int ldc,
    long sA, long sB, long sC,
    const float* __restrict__ bias,
    const void* __restrict__ resv, long sRes,
    __half* __restrict__ aux, long sAux,
    float* __restrict__ ps, float* __restrict__ ps2,
    float alpha)
{
    extern __shared__ __align__(16) __half smh[];
    __half* As = smh;                  // 3 stages A
    __half* Bs = smh + 3 * ASTG;       // 3 stages B

    const int bz = blockIdx.z;
    const int n0 = blockIdx.x * 128;
    const int m0 = blockIdx.y * 128;
    const int tid = threadIdx.x;
    const int warp = tid >> 5;
    const int lane = tid & 31;
    const int wm = warp & 1;
    const int wn = warp >> 1;
    const int g = lane >> 2;
    const int tg = lane & 3;

    const uint32_t smb = (uint32_t)__cvta_generic_to_shared(smh);

    const int a_row = lane & 15;
    const int a_kb  = (lane >> 4) << 3;
    const int b_row = lane & 7;
    const int b_kb  = ((lane >> 3) & 1) << 3;

    const __half* Ab = A + (size_t)bz * sA;
    const __half* Bb = B + (size_t)bz * sB;

    float acc[4][4][4];
    #pragma unroll
    for (int i = 0; i < 4; i++)
        #pragma unroll
        for (int j = 0; j < 4; j++)
            #pragma unroll
            for (int r = 0; r < 4; r++) acc[i][j][r] = 0.f;

    auto loadStage = [&](int st, int k0) {
        __half* Ad = As + st * ASTG;
        __half* Bd = Bs + st * ASTG;
        #pragma unroll
        for (int j = 0; j < 2; j++) {
            int id = tid + j * 256;
            int row = id >> 2, part = id & 3;
            cpa16(Ad + row * RSTR + part * 8,
                  Ab + (size_t)(m0 + row) * lda + k0 + part * 8);
            cpa16(Bd + row * RSTR + part * 8,
                  Bb + (size_t)(n0 + row) * ldb + k0 + part * 8);
        }
        asm volatile("cp.async.commit_group;\n");
    };

    const int T = K >> 5;
    loadStage(0, 0);
    if (T > 1) loadStage(1, 32);

    for (int t = 0; t < T; t++) {
        if (t + 1 < T) asm volatile("cp.async.wait_group 1;\n");
        else           asm volatile("cp.async.wait_group 0;\n");
        __syncthreads();
        if (t + 2 < T) loadStage((t + 2) % 3, (t + 2) << 5);

        const int st = t % 3;
        const uint32_t Aoff = smb + (uint32_t)(st * ASTG) * 2u;
        const uint32_t Boff = smb + (uint32_t)((3 + st) * ASTG) * 2u;
        #pragma unroll
        for (int kk = 0; kk < 32; kk += 16) {
            uint32_t a[4][4], bfr[4][2];
            #pragma unroll
            for (int mi = 0; mi < 4; mi++)
                ldsm4(a[mi], Aoff + (uint32_t)(((wm * 64 + mi * 16 + a_row) * RSTR) + kk + a_kb) * 2u);
            #pragma unroll
            for (int ni = 0; ni < 4; ni++)
                ldsm2(bfr[ni], Boff + (uint32_t)(((wn * 32 + ni * 8 + b_row) * RSTR) + kk + b_kb) * 2u);
            #pragma unroll
            for (int mi = 0; mi < 4; mi++)
                #pragma unroll
                for (int ni = 0; ni < 4; ni++)
                    mma16(acc[mi][ni], a[mi], bfr[ni]);
        }
    }

    // ---------------- epilogue ----------------
    __half* Ch = (__half*)Cv + (size_t)bz * sC;
    float*  Cf = (float*)Cv + (size_t)bz * sC;
    const float*  Rf = (EPI == 6) ? ((const float*)resv + (size_t)bz * sRes) : nullptr;
    const __half* Rh = (EPI == 7) ? ((const __half*)resv + (size_t)bz * sRes) : nullptr;

    if (EPI == 6) __syncthreads();   // stage smem reused below
    __half* smT = smh;               // [128][136] half (EPI 6)
    float*  pS  = (float*)(smh + 128 * 136);
    float*  pS2 = pS + 512;

    #pragma unroll
    for (int mi = 0; mi < 4; mi++) {
        int mr = m0 + wm * 64 + mi * 16 + g;
        float bm0 = 0.f, bm8 = 0.f;
        if (EPI == 5 || EPI == 7) { bm0 = bias[mr]; bm8 = bias[mr + 8]; }
        float rs0 = 0.f, rq0 = 0.f, rs8 = 0.f, rq8 = 0.f;
        #pragma unroll
        for (int ni = 0; ni < 4; ni++) {
            int nc = n0 + wn * 32 + ni * 8 + tg * 2;
            float v0 = acc[mi][ni][0], v1 = acc[mi][ni][1];
            float v2 = acc[mi][ni][2], v3 = acc[mi][ni][3];
            if (EPI == 1) { v0 *= alpha; v1 *= alpha; v2 *= alpha; v3 *= alpha; }
            if (EPI == 0 || EPI == 3) {
                float b0 = bias[nc], b1 = bias[nc + 1];
                v0 += b0; v1 += b1; v2 += b0; v3 += b1;
            }
            if (EPI == 3) {
                v0 = fmaxf(v0, 0.f); v1 = fmaxf(v1, 0.f);
                v2 = fmaxf(v2, 0.f); v3 = fmaxf(v3, 0.f);
            }
            if (EPI == 5 || EPI == 7) { v0 += bm0; v1 += bm0; v2 += bm8; v3 += bm8; }
            if (EPI == 7) {
                float2 r0 = __half22float2(*(const __half2*)(Rh + (size_t)mr * ldc + nc));
                float2 r8 = __half22float2(*(const __half2*)(Rh + (size_t)(mr + 8) * ldc + nc));
                v0 += r0.x; v1 += r0.y; v2 += r8.x; v3 += r8.y;
                *(float2*)(Cf + (size_t)mr * ldc + nc) = make_float2(v0, v1);
                *(float2*)(Cf + (size_t)(mr + 8) * ldc + nc) = make_float2(v2, v3);
            } else if (EPI == 6) {
                float2 r0 = *(const float2*)(Rf + (size_t)mr * ldc + nc);
                float2 r8 = *(const float2*)(Rf + (size_t)(mr + 8) * ldc + nc);
                v0 += r0.x; v1 += r0.y; v2 += r8.x; v3 += r8.y;
                *(__half2*)(Ch + (size_t)mr * ldc + nc) = __floats2half2_rn(v0, v1);
                *(__half2*)(Ch + (size_t)(mr + 8) * ldc + nc) = __floats2half2_rn(v2, v3);
                int ml = wm * 64 + mi * 16 + g;
                int nl = wn * 32 + ni * 8 + tg * 2;
                smT[(nl + 0) * 136 + ml]     = __float2half(v0);
                smT[(nl + 1) * 136 + ml]     = __float2half(v1);
                smT[(nl + 0) * 136 + ml + 8] = __float2half(v2);
                smT[(nl + 1) * 136 + ml + 8] = __float2half(v3);
                rs0 += v0 + v1; rq0 += v0 * v0 + v1 * v1;
                rs8 += v2 + v3; rq8 += v2 * v2 + v3 * v3;
            } else {
                *(__half2*)(Ch + (size_t)mr * ldc + nc) = __floats2half2_rn(v0, v1);
                *(__half2*)(Ch + (size_t)(mr + 8) * ldc + nc) = __floats2half2_rn(v2, v3);
            }
        }
        if (EPI == 6) {
            rs0 += __shfl_xor_sync(0xffffffffu, rs0, 1);
            rs0 += __shfl_xor_sync(0xffffffffu, rs0, 2);
            rq0 += __shfl_xor_sync(0xffffffffu, rq0, 1);
            rq0 += __shfl_xor_sync(0xffffffffu, rq0, 2);
            rs8 += __shfl_xor_sync(0xffffffffu, rs8, 1);
            rs8 += __shfl_xor_sync(0xffffffffu, rs8, 2);
            rq8 += __shfl_xor_sync(0xffffffffu, rq8, 1);
            rq8 += __shfl_xor_sync(0xffffffffu, rq8, 2);
            if (tg == 0) {
                int rl = wm * 64 + mi * 16 + g;
                pS [wn * 128 + rl]     = rs0;
                pS2[wn * 128 + rl]     = rq0;
                pS [wn * 128 + rl + 8] = rs8;
                pS2[wn * 128 + rl + 8] = rq8;
            }
        }
    }

    if (EPI == 6) {
        __syncthreads();
        if (tid < 128) {
            float s = pS[tid] + pS[128 + tid] + pS[256 + tid] + pS[384 + tid];
            float q = pS2[tid] + pS2[128 + tid] + pS2[256 + tid] + pS2[384 + tid];
            int slot = bz * 8 + blockIdx.x;
            ps [slot * CC + m0 + tid] = s;
            ps2[slot * CC + m0 + tid] = q;
        }
        __half* Xt = aux + (size_t)bz * sAux;
        #pragma unroll 8
        for (int it = 0; it < 32; it++) {
            int idx = it * 256 + tid;
            int row = idx >> 6, col = idx & 63;
            __half2 h = *(__half2*)(smT + row * 136 + col * 2);
            *(__half2*)(Xt + (size_t)(n0 + row) * CC + m0 + col * 2) = h;
        }
    }
}

// ---------------- elementwise / prep kernels ----------------
__global__ void bn_stats_kernel(const float* __restrict__ x,
                                const float* __restrict__ gamma,
                                const float* __restrict__ beta,
                                float* __restrict__ scale,
                                float* __restrict__ shift) {
    int c = blockIdx.x;
    int tid = threadIdx.x;
    float s = 0.f, s2 = 0.f;
    const float* xc = x + (size_t)c * HW;
    for (int b = 0; b < BB; b++) {
        const float* p = xc + (size_t)b * CC * HW;
        #pragma unroll 4
        for (int i = tid; i < HW; i += 256) {
            float v = p[i];
            s += v; s2 = fmaf(v, v, s2);
        }
    }
    __shared__ float ss[256], ss2[256];
    ss[tid] = s; ss2[tid] = s2;
    __syncthreads();
    for (int o = 128; o > 0; o >>= 1) {
        if (tid < o) { ss[tid] += ss[tid + o]; ss2[tid] += ss2[tid + o]; }
        __syncthreads();
    }
    if (tid == 0) {
        const float invN = 1.0f / (BB * HW);
        float mean = ss[0] * invN;
        float var  = ss2[0] * invN - mean * mean;
        float sc = gamma[c] * rsqrtf(var + 1e-5f);
        scale[c] = sc;
        shift[c] = beta[c] - mean * sc;
    }
}

// combine bn2 partials (256 slots) -> scale/shift
__global__ void bn2_combine(const float* __restrict__ ps, const float* __restrict__ ps2,
                            const float* __restrict__ gamma, const float* __restrict__ beta,
                            float* __restrict__ scale, float* __restrict__ shift) {
    int c = blockIdx.x * 256 + threadIdx.x;
    float s = 0.f, q = 0.f;
    for (int sl = 0; sl < 256; sl++) {
        s += ps[sl * CC + c];
        q += ps2[sl * CC + c];
    }
    const float invN = 1.0f / (BB * HW);
    float mean = s * invN;
    float var  = q * invN - mean * mean;
    float sc = gamma[c] * rsqrtf(var + 1e-5f);
    scale[c] = sc;
    shift[c] = beta[c] - mean * sc;
}

// x [c][hw] fp32 -> h^T [hw][c] half with bn1+relu
__global__ void bnT_kernel(const float* __restrict__ x, const float* __restrict__ sc,
                           const float* __restrict__ sh, __half* __restrict__ o) {
    __shared__ float t[32][33];
    int b = blockIdx.z;
    int hw0 = blockIdx.x * 32, c0 = blockIdx.y * 32;
    int tx = threadIdx.x, ty = threadIdx.y;
    const float* I = x + (size_t)b * CC * HW;
    __half* O = o + (size_t)b * HW * CC;
    #pragma unroll
    for (int j = 0; j < 32; j += 8) {
        int c = c0 + ty + j;
        float v = I[(size_t)c * HW + hw0 + tx];
        t[ty + j][tx] = fmaxf(fmaf(v, sc[c], sh[c]), 0.f);
    }
    __syncthreads();
    #pragma unroll
    for (int j = 0; j < 32; j += 8)
        O[(size_t)(hw0 + ty + j) * CC + c0 + tx] = __float2half(t[tx][ty + j]);
}

__global__ void round_half(const float* __restrict__ in, __half* __restrict__ out) {
    int i = blockIdx.x * 256 + threadIdx.x;
    float4 v = ((const float4*)in)[i];
    ((__half2*)out)[i * 2]     = __floats2half2_rn(v.x, v.y);
    ((__half2*)out)[i * 2 + 1] = __floats2half2_rn(v.z, v.w);
}

__global__ void w1_fold(const float* __restrict__ W1, const float* __restrict__ b1,
                        const float* __restrict__ sc, const float* __restrict__ sh,
                        __half* __restrict__ w1f, float* __restrict__ b1f) {
    int o = blockIdx.x;
    int tid = threadIdx.x;
    float acc = 0.f;
    for (int k = tid; k < CC; k += 256) {
        float w = W1[o * CC + k];
        acc = fmaf(w, sh[k], acc);
        w1f[o * CC + k] = __float2half(w * sc[k]);
    }
    __shared__ float r[256];
    r[tid] = acc; __syncthreads();
    for (int ofs = 128; ofs > 0; ofs >>= 1) {
        if (tid < ofs) r[tid] += r[tid + ofs];
        __syncthreads();
    }
    if (tid == 0) b1f[o] = b1[o] + r[0];
}

// row softmax over contiguous 1024-half rows of S^T, in place (axis = q)
__global__ void softmax_row(__half* __restrict__ S) {
    int row = blockIdx.x * 8 + (threadIdx.x >> 5);
    int lane = threadIdx.x & 31;
    __half2* p = (__half2*)(S + (size_t)row * HW);
    float f[32];
    #pragma unroll
    for (int i = 0; i < 16; i++) {
        float2 v = __half22float2(p[i * 32 + lane]);
        f[i * 2] = v.x; f[i * 2 + 1] = v.y;
    }
    float m = -3.0e38f;
    #pragma unroll
    for (int i = 0; i < 32; i++) m = fmaxf(m, f[i]);
    #pragma unroll
    for (int o = 16; o > 0; o >>= 1) m = fmaxf(m, __shfl_xor_sync(0xffffffffu, m, o));
    float s = 0.f;
    #pragma unroll
    for (int i = 0; i < 32; i++) { f[i] = fexp(f[i] - m); s += f[i]; }
    #pragma unroll
    for (int o = 16; o > 0; o >>= 1) s += __shfl_xor_sync(0xffffffffu, s, o);
    float inv = 1.0f / s;
    #pragma unroll
    for (int i = 0; i < 16; i++)
        p[i * 32 + lane] = __floats2half2_rn(f[i * 2] * inv, f[i * 2 + 1] * inv);
}

// ---------------- launcher ----------------
extern "C" void kernel_launch(void* const* d_in, const int* in_sizes, int n_in,
                              void* d_out, int out_size) {
    const float* x     = (const float*)d_in[0];
    const float* bn1_g = (const float*)d_in[1];
    const float* bn1_b = (const float*)d_in[2];
    const float* W_qkv = (const float*)d_in[3];
    const float* b_qkv = (const float*)d_in[4];
    const float* bn2_g = (const float*)d_in[5];
    const float* bn2_b = (const float*)d_in[6];
    const float* W1    = (const float*)d_in[7];
    const float* b1    = (const float*)d_in[8];
    const float* W2    = (const float*)d_in[9];
    const float* b2    = (const float*)d_in[10];
    float* out = (float*)d_out;

    __half *p_ht, *p_qkt, *p_v, *p_st, *p_xr, *p_xrt, *p_zt, *p_wqh, *p_w1f, *p_w2h;
    float *p_b1f, *p_s1, *p_h1, *p_s2, *p_h2, *p_ps, *p_ps2;
    cudaGetSymbolAddress((void**)&p_ht,  g_ht);
    cudaGetSymbolAddress((void**)&p_qkt, g_qkt);
    cudaGetSymbolAddress((void**)&p_v,   g_v);
    cudaGetSymbolAddress((void**)&p_st,  g_st);
    cudaGetSymbolAddress((void**)&p_xr,  g_xr);
    cudaGetSymbolAddress((void**)&p_xrt, g_xrt);
    cudaGetSymbolAddress((void**)&p_zt,  g_zt);
    cudaGetSymbolAddress((void**)&p_wqh, g_wqh);
    cudaGetSymbolAddress((void**)&p_w1f, g_w1f);
    cudaGetSymbolAddress((void**)&p_w2h, g_w2h);
    cudaGetSymbolAddress((void**)&p_b1f, g_b1f);
    cudaGetSymbolAddress((void**)&p_s1,  g_s1);
    cudaGetSymbolAddress((void**)&p_h1,  g_h1);
    cudaGetSymbolAddress((void**)&p_s2,  g_s2);
    cudaGetSymbolAddress((void**)&p_h2,  g_h2);
    cudaGetSymbolAddress((void**)&p_ps,  g_psum);
    cudaGetSymbolAddress((void**)&p_ps2, g_psum2);

    cudaFuncSetAttribute(hgemm<0>, cudaFuncAttributeMaxDynamicSharedMemorySize, SMB);
    cudaFuncSetAttribute(hgemm<1>, cudaFuncAttributeMaxDynamicSharedMemorySize, SMB);
    cudaFuncSetAttribute(hgemm<3>, cudaFuncAttributeMaxDynamicSharedMemorySize, SMB);
    cudaFuncSetAttribute(hgemm<5>, cudaFuncAttributeMaxDynamicSharedMemorySize, SMB);
    cudaFuncSetAttribute(hgemm<6>, cudaFuncAttributeMaxDynamicSharedMemorySize, SMB);
    cudaFuncSetAttribute(hgemm<7>, cudaFuncAttributeMaxDynamicSharedMemorySize, SMB);

    const long sX  = (long)CC * HW;
    const long sHT = (long)HW * CC;
    const long sQK = (long)HW * 128;
    const long sS  = (long)HW * HW;

    // prep: weights to half, bn1 stats, h^T
    round_half<<<OO * CC / 1024, 256>>>(W_qkv, p_wqh);
    round_half<<<CC * CC / 1024, 256>>>(W2, p_w2h);
    bn_stats_kernel<<<CC, 256>>>(x, bn1_g, bn1_b, p_s1, p_h1);
    bnT_kernel<<<dim3(HW / 32, CC / 32, BB), dim3(32, 8)>>>(x, p_s1, p_h1, p_ht);

    // qk[hw][128] = h^T . Wqk^T + b_qkv[0:128]
    hgemm<0><<<dim3(1, 8, BB), 256, SMB>>>(
        p_ht, p_wqh, p_qkt, CC, CC, CC, 128,
        sHT, 0L, sQK, b_qkv, nullptr, 0L, nullptr, 0L, nullptr, nullptr, 1.0f);

    // V[c][hw] = Wv . h + b_qkv[128+c]
    hgemm<5><<<dim3(8, 4, BB), 256, SMB>>>(
        p_wqh + 128 * CC, p_ht, p_v, CC, CC, CC, HW,
        0L, sHT, sX, b_qkv + 128, nullptr, 0L, nullptr, 0L, nullptr, nullptr, 1.0f);

    // S^T[k'][q] = (K . Q^T)/8
    hgemm<1><<<dim3(8, 8, BB), 256, SMB>>>(
        p_qkt + 64, p_qkt, p_st, DD, 128, 128, HW,
        sQK, sQK, sS, nullptr, nullptr, 0L, nullptr, 0L, nullptr, nullptr, 0.125f);

    // P^T row softmax in place
    softmax_row<<<BB * HW / 8, 256>>>(p_st);

    // xr(half) = x + V . P ; fused: xrt (transposed half) + bn2 partial sums
    hgemm<6><<<dim3(8, 4, BB), 256, SMB>>>(
        p_v, p_st, p_xr, HW, HW, HW, HW,
        sX, sS, sX, nullptr, x, sX, p_xrt, sHT, p_ps, p_ps2, 1.0f);

    // bn2 combine + fold into W1
    bn2_combine<<<2, 256>>>(p_ps, p_ps2, bn2_g, bn2_b, p_s2, p_h2);
    w1_fold<<<CC, 256>>>(W1, b1, p_s2, p_h2, p_w1f, p_b1f);

    // z^T[hw][o] = relu(xr^T . W1'^T + b1')
    hgemm<3><<<dim3(4, 8, BB), 256, SMB>>>(
        p_xrt, p_w1f, p_zt, CC, CC, CC, CC,
        sHT, 0L, sHT, p_b1f, nullptr, 0L, nullptr, 0L, nullptr, nullptr, 1.0f);

    // out[c][hw] = xr(half) + W2 . z + b2
    hgemm<7><<<dim3(8, 4, BB), 256, SMB>>>(
        p_w2h, p_zt, out, CC, CC, CC, HW,
        0L, sHT, sX, b2, p_xr, sX, nullptr, 0L, nullptr, nullptr, 1.0f);
}

// round 15
// speedup vs baseline: 1.0850x; 1.0052x over previous
#include <cuda_runtime.h>
#include <cuda_fp16.h>
#include <math.h>
#include <stdint.h>

#define BB 32
#define CC 512
#define HW 1024
#define DD 64
#define OO 640

// ---------------- scratch (device globals) ----------------
__device__ __half g_ht[(size_t)BB * HW * CC];    // h1^T [b][hw][c]
__device__ __half g_qkt[(size_t)BB * HW * 128];  // [b][hw][0:64=q,64:128=k]
__device__ __half g_v[(size_t)BB * CC * HW];     // V [b][c][hw]
__device__ __half g_st[(size_t)BB * HW * HW];    // S^T then P^T [b][k'][q]
__device__ __half g_xr[(size_t)BB * CC * HW];    // xr HALF [b][c][hw]
__device__ __half g_xrt[(size_t)BB * HW * CC];   // xr^T half [b][hw][c]
__device__ __half g_zt[(size_t)BB * HW * CC];    // z^T [b][hw][o]
__device__ __half g_wqh[OO * CC];                // W_qkv half [o][c]
__device__ __half g_w1f[CC * CC];                // (W1*bn2sc) half [o][c]
__device__ __half g_w2h[CC * CC];                // W2 half [c][o]
__device__ float  g_b1f[CC];
__device__ float  g_s1[CC], g_h1[CC], g_s2[CC], g_h2[CC];
__device__ float  g_psum[256 * CC];              // bn2 partials [slot][c]
__device__ float  g_psum2[256 * CC];

// ---------------- helpers ----------------
__device__ __forceinline__ float fexp(float x) {
    x = fmaxf(x, -87.0f);
    float t  = x * 1.4426950408889634f;
    float fi = floorf(t);
    float f  = t - fi;
    float r = 1.5403530e-4f;
    r = fmaf(r, f, 1.3333558e-3f);
    r = fmaf(r, f, 9.6181291e-3f);
    r = fmaf(r, f, 5.5504109e-2f);
    r = fmaf(r, f, 2.4022651e-1f);
    r = fmaf(r, f, 6.9314718e-1f);
    r = fmaf(r, f, 1.0f);
    return r * __int_as_float(((int)fi + 127) << 23);
}
__device__ __forceinline__ void cpa16(void* s, const void* g) {
    unsigned ss = (unsigned)__cvta_generic_to_shared(s);
    asm volatile("cp.async.cg.shared.global [%0], [%1], 16;\n" :: "r"(ss), "l"(g));
}
__device__ __forceinline__ void mma16(float* c, const uint32_t* a, const uint32_t* b) {
    asm volatile(
        "mma.sync.aligned.m16n8k16.row.col.f32.f16.f16.f32 "
        "{%0,%1,%2,%3}, {%4,%5,%6,%7}, {%8,%9}, {%0,%1,%2,%3};\n"
        : "+f"(c[0]), "+f"(c[1]), "+f"(c[2]), "+f"(c[3])
        : "r"(a[0]), "r"(a[1]), "r"(a[2]), "r"(a[3]), "r"(b[0]), "r"(b[1]));
}
__device__ __forceinline__ void ldsm4(uint32_t* r, uint32_t addr) {
    asm volatile("ldmatrix.sync.aligned.m8n8.x4.shared.b16 {%0,%1,%2,%3}, [%4];"
        : "=r"(r[0]), "=r"(r[1]), "=r"(r[2]), "=r"(r[3]) : "r"(addr));
}
__device__ __forceinline__ void ldsm2(uint32_t* r, uint32_t addr) {
    asm volatile("ldmatrix.sync.aligned.m8n8.x2.shared.b16 {%0,%1}, [%2];"
        : "=r"(r[0]), "=r"(r[1]) : "r"(addr));
}

// ---------------- fp16 tensor GEMM ----------------
// C[m,n] = alpha * sum_k A[m][k] * B[n][k]; CTA 128x128, 8 warps (2m x 4n),
// k-stage 32, 3-stage cp.async ring, occupancy 2.  (R10 mainloop, unchanged)
// EPI: 0 = half store + bias[n]
//      1 = half store * alpha
//      3 = half store + bias[n] + relu
//      5 = half store + bias[m]
//      6 = half store + fp32 res, plus: xrt (half, transposed) + bn2 partials
//      7 = fp32 store + bias[m] + half res
#define RSTR 40                    // 32 + 8 halves pad
#define ASTG (128 * RSTR)
#define SMB  (3 * 2 * ASTG * 2)    // 61440 bytes

template <int EPI>
__global__ void __launch_bounds__(256, 2) hgemm(
    const __half* __restrict__ A, const __half* __restrict__ B, void* __restrict__ Cv,
    int K, int lda, int ldb, int ldc,
    long sA, long sB, long sC,
    const float* __restrict__ bias,
    const void* __restrict__ resv, long sRes,
    __half* __restrict__ aux, long sAux,
    float* __restrict__ ps, float* __restrict__ ps2,
    float alpha)
{
    extern __shared__ __align__(16) __half smh[];
    __half* As = smh;                  // 3 stages A
    __half* Bs = smh + 3 * ASTG;       // 3 stages B

    const int bz = blockIdx.z;
    const int n0 = blockIdx.x * 128;
    const int m0 = blockIdx.y * 128;
    const int tid = threadIdx.x;
    const int warp = tid >> 5;
    const int lane = tid & 31;
    const int wm = warp & 1;
    const int wn = warp >> 1;
    const int g = lane >> 2;
    const int tg = lane & 3;

    const uint32_t smb = (uint32_t)__cvta_generic_to_shared(smh);

    const int a_row = lane & 15;
    const int a_kb  = (lane >> 4) << 3;
    const int b_row = lane & 7;
    const int b_kb  = ((lane >> 3) & 1) << 3;

    const __half* Ab = A + (size_t)bz * sA;
    const __half* Bb = B + (size_t)bz * sB;

    float acc[4][4][4];
    #pragma unroll
    for (int i = 0; i < 4; i++)
        #pragma unroll
        for (int j = 0; j < 4; j++)
            #pragma unroll
            for (int r = 0; r < 4; r++) acc[i][j][r] = 0.f;

    auto loadStage = [&](int st, int k0) {
        __half* Ad = As + st * ASTG;
        __half* Bd = Bs + st * ASTG;
        #pragma unroll
        for (int j = 0; j < 2; j++) {
            int id = tid + j * 256;
            int row = id >> 2, part = id & 3;
            cpa16(Ad + row * RSTR + part * 8,
                  Ab + (size_t)(m0 + row) * lda + k0 + part * 8);
            cpa16(Bd + row * RSTR + part * 8,
                  Bb + (size_t)(n0 + row) * ldb + k0 + part * 8);
        }
        asm volatile("cp.async.commit_group;\n");
    };

    const int T = K >> 5;
    loadStage(0, 0);
    if (T > 1) loadStage(1, 32);

    for (int t = 0; t < T; t++) {
        if (t + 1 < T) asm volatile("cp.async.wait_group 1;\n");
        else           asm volatile("cp.async.wait_group 0;\n");
        __syncthreads();
        if (t + 2 < T) loadStage((t + 2) % 3, (t + 2) << 5);

        const int st = t % 3;
        const uint32_t Aoff = smb + (uint32_t)(st * ASTG) * 2u;
        const uint32_t Boff = smb + (uint32_t)((3 + st) * ASTG) * 2u;
        #pragma unroll
        for (int kk = 0; kk < 32; kk += 16) {
            uint32_t a[4][4], bfr[4][2];
            #pragma unroll
            for (int mi = 0; mi < 4; mi++)
                ldsm4(a[mi], Aoff + (uint32_t)(((wm * 64 + mi * 16 + a_row) * RSTR) + kk + a_kb) * 2u);
            #pragma unroll
            for (int ni = 0; ni < 4; ni++)
                ldsm2(bfr[ni], Boff + (uint32_t)(((wn * 32 + ni * 8 + b_row) * RSTR) + kk + b_kb) * 2u);
            #pragma unroll
            for (int mi = 0; mi < 4; mi++)
                #pragma unroll
                for (int ni = 0; ni < 4; ni++)
                    mma16(acc[mi][ni], a[mi], bfr[ni]);
        }
    }

    // ---------------- epilogue ----------------
    __half* Ch = (__half*)Cv + (size_t)bz * sC;
    float*  Cf = (float*)Cv + (size_t)bz * sC;
    const float*  Rf = (EPI == 6) ? ((const float*)resv + (size_t)bz * sRes) : nullptr;
    const __half* Rh = (EPI == 7) ? ((const __half*)resv + (size_t)bz * sRes) : nullptr;

    if (EPI == 6) __syncthreads();   // stage smem reused below
    __half* smT = smh;               // [128][136] half (EPI 6)
    float*  pS  = (float*)(smh + 128 * 136);
    float*  pS2 = pS + 512;

    #pragma unroll
    for (int mi = 0; mi < 4; mi++) {
        int mr = m0 + wm * 64 + mi * 16 + g;
        float bm0 = 0.f, bm8 = 0.f;
        if (EPI == 5 || EPI == 7) { bm0 = bias[mr]; bm8 = bias[mr + 8]; }
        float rs0 = 0.f, rq0 = 0.f, rs8 = 0.f, rq8 = 0.f;
        #pragma unroll
        for (int ni = 0; ni < 4; ni++) {
            int nc = n0 + wn * 32 + ni * 8 + tg * 2;
            float v0 = acc[mi][ni][0], v1 = acc[mi][ni][1];
            float v2 = acc[mi][ni][2], v3 = acc[mi][ni][3];
            if (EPI == 1) { v0 *= alpha; v1 *= alpha; v2 *= alpha; v3 *= alpha; }
            if (EPI == 0 || EPI == 3) {
                float b0 = bias[nc], b1 = bias[nc + 1];
                v0 += b0; v1 += b1; v2 += b0; v3 += b1;
            }
            if (EPI == 3) {
                v0 = fmaxf(v0, 0.f); v1 = fmaxf(v1, 0.f);
                v2 = fmaxf(v2, 0.f); v3 = fmaxf(v3, 0.f);
            }
            if (EPI == 5 || EPI == 7) { v0 += bm0; v1 += bm0; v2 += bm8; v3 += bm8; }
            if (EPI == 7) {
                float2 r0 = __half22float2(*(const __half2*)(Rh + (size_t)mr * ldc + nc));
                float2 r8 = __half22float2(*(const __half2*)(Rh + (size_t)(mr + 8) * ldc + nc));
                v0 += r0.x; v1 += r0.y; v2 += r8.x; v3 += r8.y;
                *(float2*)(Cf + (size_t)mr * ldc + nc) = make_float2(v0, v1);
                *(float2*)(Cf + (size_t)(mr + 8) * ldc + nc) = make_float2(v2, v3);
            } else if (EPI == 6) {
                float2 r0 = *(const float2*)(Rf + (size_t)mr * ldc + nc);
                float2 r8 = *(const float2*)(Rf + (size_t)(mr + 8) * ldc + nc);
                v0 += r0.x; v1 += r0.y; v2 += r8.x; v3 += r8.y;
                *(__half2*)(Ch + (size_t)mr * ldc + nc) = __floats2half2_rn(v0, v1);
                *(__half2*)(Ch + (size_t)(mr + 8) * ldc + nc) = __floats2half2_rn(v2, v3);
                int ml = wm * 64 + mi * 16 + g;
                int nl = wn * 32 + ni * 8 + tg * 2;
                smT[(nl + 0) * 136 + ml]     = __float2half(v0);
                smT[(nl + 1) * 136 + ml]     = __float2half(v1);
                smT[(nl + 0) * 136 + ml + 8] = __float2half(v2);
                smT[(nl + 1) * 136 + ml + 8] = __float2half(v3);
                rs0 += v0 + v1; rq0 += v0 * v0 + v1 * v1;
                rs8 += v2 + v3; rq8 += v2 * v2 + v3 * v3;
            } else {
                *(__half2*)(Ch + (size_t)mr * ldc + nc) = __floats2half2_rn(v0, v1);
                *(__half2*)(Ch + (size_t)(mr + 8) * ldc + nc) = __floats2half2_rn(v2, v3);
            }
        }
        if (EPI == 6) {
            rs0 += __shfl_xor_sync(0xffffffffu, rs0, 1);
            rs0 += __shfl_xor_sync(0xffffffffu, rs0, 2);
            rq0 += __shfl_xor_sync(0xffffffffu, rq0, 1);
            rq0 += __shfl_xor_sync(0xffffffffu, rq0, 2);
            rs8 += __shfl_xor_sync(0xffffffffu, rs8, 1);
            rs8 += __shfl_xor_sync(0xffffffffu, rs8, 2);
            rq8 += __shfl_xor_sync(0xffffffffu, rq8, 1);
            rq8 += __shfl_xor_sync(0xffffffffu, rq8, 2);
            if (tg == 0) {
                int rl = wm * 64 + mi * 16 + g;
                pS [wn * 128 + rl]     = rs0;
                pS2[wn * 128 + rl]     = rq0;
                pS [wn * 128 + rl + 8] = rs8;
                pS2[wn * 128 + rl + 8] = rq8;
            }
        }
    }

    if (EPI == 6) {
        __syncthreads();
        if (tid < 128) {
            float s = pS[tid] + pS[128 + tid] + pS[256 + tid] + pS[384 + tid];
            float q = pS2[tid] + pS2[128 + tid] + pS2[256 + tid] + pS2[384 + tid];
            int slot = bz * 8 + blockIdx.x;
            ps [slot * CC + m0 + tid] = s;
            ps2[slot * CC + m0 + tid] = q;
        }
        __half* Xt = aux + (size_t)bz * sAux;
        #pragma unroll 8
        for (int it = 0; it < 32; it++) {
            int idx = it * 256 + tid;
            int row = idx >> 6, col = idx & 63;
            __half2 h = *(__half2*)(smT + row * 136 + col * 2);
            *(__half2*)(Xt + (size_t)(n0 + row) * CC + m0 + col * 2) = h;
        }
    }
}

// ---------------- elementwise / prep kernels ----------------
__global__ void bn_stats_kernel(const float* __restrict__ x,
                                const float* __restrict__ gamma,
                                const float* __restrict__ beta,
                                float* __restrict__ scale,
                                float* __restrict__ shift) {
    int c = blockIdx.x;
    int tid = threadIdx.x;
    float s = 0.f, s2 = 0.f;
    const float* xc = x + (size_t)c * HW;
    for (int b = 0; b < BB; b++) {
        const float* p = xc + (size_t)b * CC * HW;
        #pragma unroll 4
        for (int i = tid; i < HW; i += 256) {
            float v = p[i];
            s += v; s2 = fmaf(v, v, s2);
        }
    }
    __shared__ float ss[256], ss2[256];
    ss[tid] = s; ss2[tid] = s2;
    __syncthreads();
    for (int o = 128; o > 0; o >>= 1) {
        if (tid < o) { ss[tid] += ss[tid + o]; ss2[tid] += ss2[tid + o]; }
        __syncthreads();
    }
    if (tid == 0) {
        const float invN = 1.0f / (BB * HW);
        float mean = ss[0] * invN;
        float var  = ss2[0] * invN - mean * mean;
        float sc = gamma[c] * rsqrtf(var + 1e-5f);
        scale[c] = sc;
        shift[c] = beta[c] - mean * sc;
    }
}

// combine bn2 partials (256 slots) -> scale/shift
__global__ void bn2_combine(const float* __restrict__ ps, const float* __restrict__ ps2,
                            const float* __restrict__ gamma, const float* __restrict__ beta,
                            float* __restrict__ scale, float* __restrict__ shift) {
    int c = blockIdx.x * 256 + threadIdx.x;
    float s = 0.f, q = 0.f;
    for (int sl = 0; sl < 256; sl++) {
        s += ps[sl * CC + c];
        q += ps2[sl * CC + c];
    }
    const float invN = 1.0f / (BB * HW);
    float mean = s * invN;
    float var  = q * invN - mean * mean;
    float sc = gamma[c] * rsqrtf(var + 1e-5f);
    scale[c] = sc;
    shift[c] = beta[c] - mean * sc;
}

// x [c][hw] fp32 -> h^T [hw][c] half with bn1+relu
__global__ void bnT_kernel(const float* __restrict__ x, const float* __restrict__ sc,
                           const float* __restrict__ sh, __half* __restrict__ o) {
    __shared__ float t[32][33];
    int b = blockIdx.z;
    int hw0 = blockIdx.x * 32, c0 = blockIdx.y * 32;
    int tx = threadIdx.x, ty = threadIdx.y;
    const float* I = x + (size_t)b * CC * HW;
    __half* O = o + (size_t)b * HW * CC;
    #pragma unroll
    for (int j = 0; j < 32; j += 8) {
        int c = c0 + ty + j;
        float v = I[(size_t)c * HW + hw0 + tx];
        t[ty + j][tx] = fmaxf(fmaf(v, sc[c], sh[c]), 0.f);
    }
    __syncthreads();
    #pragma unroll
    for (int j = 0; j < 32; j += 8)
        O[(size_t)(hw0 + ty + j) * CC + c0 + tx] = __float2half(t[tx][ty + j]);
}

__global__ void round_half(const float* __restrict__ in, __half* __restrict__ out) {
    int i = blockIdx.x * 256 + threadIdx.x;
    float4 v = ((const float4*)in)[i];
    ((__half2*)out)[i * 2]     = __floats2half2_rn(v.x, v.y);
    ((__half2*)out)[i * 2 + 1] = __floats2half2_rn(v.z, v.w);
}

__global__ void w1_fold(const float* __restrict__ W1, const float* __restrict__ b1,
                        const float* __restrict__ sc, const float* __restrict__ sh,
                        __half* __restrict__ w1f, float* __restrict__ b1f) {
    int o = blockIdx.x;
    int tid = threadIdx.x;
    float acc = 0.f;
    for (int k = tid; k < CC; k += 256) {
        float w = W1[o * CC + k];
        acc = fmaf(w, sh[k], acc);
        w1f[o * CC + k] = __float2half(w * sc[k]);
    }
    __shared__ float r[256];
    r[tid] = acc; __syncthreads();
    for (int ofs = 128; ofs > 0; ofs >>= 1) {
        if (tid < ofs) r[tid] += r[tid + ofs];
        __syncthreads();
    }
    if (tid == 0) b1f[o] = b1[o] + r[0];
}

// row softmax over contiguous 1024-half rows of S^T, in place (axis = q)
__global__ void softmax_row(__half* __restrict__ S) {
    int row = blockIdx.x * 8 + (threadIdx.x >> 5);
    int lane = threadIdx.x & 31;
    __half2* p = (__half2*)(S + (size_t)row * HW);
    float f[32];
    #pragma unroll
    for (int i = 0; i < 16; i++) {
        float2 v = __half22float2(p[i * 32 + lane]);
        f[i * 2] = v.x; f[i * 2 + 1] = v.y;
    }
    float m = -3.0e38f;
    #pragma unroll
    for (int i = 0; i < 32; i++) m = fmaxf(m, f[i]);
    #pragma unroll
    for (int o = 16; o > 0; o >>= 1) m = fmaxf(m, __shfl_xor_sync(0xffffffffu, m, o));
    float s = 0.f;
    #pragma unroll
    for (int i = 0; i < 32; i++) { f[i] = fexp(f[i] - m); s += f[i]; }
    #pragma unroll
    for (int o = 16; o > 0; o >>= 1) s += __shfl_xor_sync(0xffffffffu, s, o);
    float inv = 1.0f / s;
    #pragma unroll
    for (int i = 0; i < 16; i++)
        p[i * 32 + lane] = __floats2half2_rn(f[i * 2] * inv, f[i * 2 + 1] * inv);
}

// ---------------- launcher (multi-stream overlap: V-GEMM ∥ qk→S→softmax) ----------------
extern "C" void kernel_launch(void* const* d_in, const int* in_sizes, int n_in,
                              void* d_out, int out_size) {
    const float* x     = (const float*)d_in[0];
    const float* bn1_g = (const float*)d_in[1];
    const float* bn1_b = (const float*)d_in[2];
    const float* W_qkv = (const float*)d_in[3];
    const float* b_qkv = (const float*)d_in[4];
    const float* bn2_g = (const float*)d_in[5];
    const float* bn2_b = (const float*)d_in[6];
    const float* W1    = (const float*)d_in[7];
    const float* b1    = (const float*)d_in[8];
    const float* W2    = (const float*)d_in[9];
    const float* b2    = (const float*)d_in[10];
    float* out = (float*)d_out;

    __half *p_ht, *p_qkt, *p_v, *p_st, *p_xr, *p_xrt, *p_zt, *p_wqh, *p_w1f, *p_w2h;
    float *p_b1f, *p_s1, *p_h1, *p_s2, *p_h2, *p_ps, *p_ps2;
    cudaGetSymbolAddress((void**)&p_ht,  g_ht);
    cudaGetSymbolAddress((void**)&p_qkt, g_qkt);
    cudaGetSymbolAddress((void**)&p_v,   g_v);
    cudaGetSymbolAddress((void**)&p_st,  g_st);
    cudaGetSymbolAddress((void**)&p_xr,  g_xr);
    cudaGetSymbolAddress((void**)&p_xrt, g_xrt);
    cudaGetSymbolAddress((void**)&p_zt,  g_zt);
    cudaGetSymbolAddress((void**)&p_wqh, g_wqh);
    cudaGetSymbolAddress((void**)&p_w1f, g_w1f);
    cudaGetSymbolAddress((void**)&p_w2h, g_w2h);
    cudaGetSymbolAddress((void**)&p_b1f, g_b1f);
    cudaGetSymbolAddress((void**)&p_s1,  g_s1);
    cudaGetSymbolAddress((void**)&p_h1,  g_h1);
    cudaGetSymbolAddress((void**)&p_s2,  g_s2);
    cudaGetSymbolAddress((void**)&p_h2,  g_h2);
    cudaGetSymbolAddress((void**)&p_ps,  g_psum);
    cudaGetSymbolAddress((void**)&p_ps2, g_psum2);

    cudaFuncSetAttribute(hgemm<0>, cudaFuncAttributeMaxDynamicSharedMemorySize, SMB);
    cudaFuncSetAttribute(hgemm<1>, cudaFuncAttributeMaxDynamicSharedMemorySize, SMB);
    cudaFuncSetAttribute(hgemm<3>, cudaFuncAttributeMaxDynamicSharedMemorySize, SMB);
    cudaFuncSetAttribute(hgemm<5>, cudaFuncAttributeMaxDynamicSharedMemorySize, SMB);
    cudaFuncSetAttribute(hgemm<6>, cudaFuncAttributeMaxDynamicSharedMemorySize, SMB);
    cudaFuncSetAttribute(hgemm<7>, cudaFuncAttributeMaxDynamicSharedMemorySize, SMB);

    const long sX  = (long)CC * HW;
    const long sHT = (long)HW * CC;
    const long sQK = (long)HW * 128;
    const long sS  = (long)HW * HW;

    // side stream + fork/join events (no device memory; fresh per call)
    cudaStream_t s1;
    cudaStreamCreateWithFlags(&s1, cudaStreamNonBlocking);
    cudaEvent_t evFork, evJoin;
    cudaEventCreateWithFlags(&evFork, cudaEventDisableTiming);
    cudaEventCreateWithFlags(&evJoin, cudaEventDisableTiming);

    // prep: weights to half, bn1 stats, h^T  (main stream)
    round_half<<<OO * CC / 1024, 256>>>(W_qkv, p_wqh);
    round_half<<<CC * CC / 1024, 256>>>(W2, p_w2h);
    bn_stats_kernel<<<CC, 256>>>(x, bn1_g, bn1_b, p_s1, p_h1);
    bnT_kernel<<<dim3(HW / 32, CC / 32, BB), dim3(32, 8)>>>(x, p_s1, p_h1, p_ht);

    // fork: V-GEMM depends only on ht + wqh
    cudaEventRecord(evFork, 0);
    cudaStreamWaitEvent(s1, evFork, 0);

    // [s1] V[c][hw] = Wv . h + b_qkv[128+c]
    hgemm<5><<<dim3(8, 4, BB), 256, SMB, s1>>>(
        p_wqh + 128 * CC, p_ht, p_v, CC, CC, CC, HW,
        0L, sHT, sX, b_qkv + 128, nullptr, 0L, nullptr, 0L, nullptr, nullptr, 1.0f);
    cudaEventRecord(evJoin, s1);

    // [s0] qk[hw][128] = h^T . Wqk^T + b_qkv[0:128]
    hgemm<0><<<dim3(1, 8, BB), 256, SMB>>>(
        p_ht, p_wqh, p_qkt, CC, CC, CC, 128,
        sHT, 0L, sQK, b_qkv, nullptr, 0L, nullptr, 0L, nullptr, nullptr, 1.0f);

    // [s0] S^T[k'][q] = (K . Q^T)/8
    hgemm<1><<<dim3(8, 8, BB), 256, SMB>>>(
        p_qkt + 64, p_qkt, p_st, DD, 128, 128, HW,
        sQK, sQK, sS, nullptr, nullptr, 0L, nullptr, 0L, nullptr, nullptr, 0.125f);

    // [s0] P^T row softmax in place
    softmax_row<<<BB * HW / 8, 256>>>(p_st);

    // join: attention GEMM needs both V (s1) and P (s0)
    cudaStreamWaitEvent(0, evJoin, 0);

    // xr(half) = x + V . P ; fused: xrt (transposed half) + bn2 partial sums
    hgemm<6><<<dim3(8, 4, BB), 256, SMB>>>(
        p_v, p_st, p_xr, HW, HW, HW, HW,
        sX, sS, sX, nullptr, x, sX, p_xrt, sHT, p_ps, p_ps2, 1.0f);

    // bn2 combine + fold into W1
    bn2_combine<<<2, 256>>>(p_ps, p_ps2, bn2_g, bn2_b, p_s2, p_h2);
    w1_fold<<<CC, 256>>>(W1, b1, p_s2, p_h2, p_w1f, p_b1f);

    // z^T[hw][o] = relu(xr^T . W1'^T + b1')
    hgemm<3><<<dim3(4, 8, BB), 256, SMB>>>(
        p_xrt, p_w1f, p_zt, CC, CC, CC, CC,
        sHT, 0L, sHT, p_b1f, nullptr, 0L, nullptr, 0L, nullptr, nullptr, 1.0f);

    // out[c][hw] = xr(half) + W2 . z + b2
    hgemm<7><<<dim3(8, 4, BB), 256, SMB>>>(
        p_w2h, p_zt, out, CC, CC, CC, HW,
        0L, sHT, sX, b2, p_xr, sX, nullptr, 0L, nullptr, nullptr, 1.0f);
}